// round 14
// baseline (speedup 1.0000x reference)
#include <cuda_runtime.h>
#include <cuda_fp16.h>
#include <cstdint>

#define N_NODES 100000
#define N_EDGES 3200000
#define D       64
#define NH      128

// ---------------------------------------------------------------------------
// Scratch (allocation-free rule: __device__ globals)
// ---------------------------------------------------------------------------
__device__ __half g_Ah[(size_t)N_NODES * NH];   // 25.6 MB: W1[:, :64] @ z + b1  (fp16)
__device__ __half g_Bh[(size_t)N_NODES * NH];   // 25.6 MB: W1[:, 64:] @ z       (fp16)

// ---------------------------------------------------------------------------
// smem layout for node_mma (bytes)
// ---------------------------------------------------------------------------
#define SM_B1   0            // 512 B
#define SM_ZH   512          // 16 KB  zh [128 rows][128 B]
#define SM_WH   16896        // 32 KB  Wh [256 rows][128 B]  (fused, swizzled)
#define SM_TOT  49664

// ---------------------------------------------------------------------------
// m16n8k16 fp16 MMA, fp32 accumulators (sm_80+ PTX, portable to compute_103)
// ---------------------------------------------------------------------------
__device__ __forceinline__ void mma16816(float* c, const uint32_t* a,
                                         uint32_t b0, uint32_t b1) {
    asm volatile(
        "mma.sync.aligned.m16n8k16.row.col.f32.f16.f16.f32 "
        "{%0,%1,%2,%3}, {%4,%5,%6,%7}, {%8,%9}, {%0,%1,%2,%3};"
        : "+f"(c[0]), "+f"(c[1]), "+f"(c[2]), "+f"(c[3])
        : "r"(a[0]), "r"(a[1]), "r"(a[2]), "r"(a[3]), "r"(b0), "r"(b1));
}

// ---------------------------------------------------------------------------
// Kernel 1: node GEMM on tensor cores (fused W conversion, single fp16 MMA).
// D[128 nodes x 256 cols] = zh[128x64] @ Wh[64x256]  (fp32 accum)
// ---------------------------------------------------------------------------
__global__ void __launch_bounds__(256) node_mma(const float* __restrict__ z,
                                                const float* __restrict__ W1,
                                                const float* __restrict__ b1) {
    extern __shared__ char smem[];
    const int tid  = threadIdx.x;
    const int wid  = tid >> 5;
    const int lane = tid & 31;
    const int gr   = lane >> 2;   // group row 0..7
    const int cc   = lane & 3;    // thread-in-group 0..3
    const int nodeBase = blockIdx.x * 128;

    if (tid < 128) ((float*)(smem + SM_B1))[tid] = b1[tid];

    // Fused W conversion: W1 fp32 -> swizzled fp16 smem (coalesced L2 reads)
    #pragma unroll
    for (int it = 0; it < 64; it++) {
        int idx = tid + it * 256;       // 0..16383
        int n = idx >> 6;
        int k = idx & 63;
        float w = (n < 128) ? W1[n * NH + k] : W1[(n - 128) * NH + 64 + k];
        uint32_t off = (uint32_t)(n * 128 + ((k * 2) ^ ((n & 7) << 4)));
        *(__half*)(smem + SM_WH + off) = __float2half_rn(w);
    }

    // z tile: 128 rows x 64 cols fp32 -> zh fp16, swizzled
    #pragma unroll
    for (int i = 0; i < 16; i++) {
        int p    = tid + i * 256;
        int r    = p >> 5;
        int kp   = p & 31;
        int node = nodeBase + r;
        float2 zv = (node < N_NODES)
                  ? ((const float2*)z)[(size_t)node * 32 + kp]
                  : make_float2(0.f, 0.f);
        __half2 h = __floats2half2_rn(zv.x, zv.y);
        uint32_t off = (uint32_t)(r * 128 + ((4 * kp) ^ ((r & 7) << 4)));
        *(uint32_t*)(smem + SM_ZH + off) = *(const uint32_t*)&h;
    }
    __syncthreads();

    const int rowlo = wid * 16 + gr;
    const int rowhi = rowlo + 8;
    const int sw    = gr << 4;
    uint32_t aH[4][4];
    #pragma unroll
    for (int ks = 0; ks < 4; ks++) {
        int k0 = ks * 32 + 4 * cc;
        int oLo = k0 ^ sw, oHi = (k0 + 16) ^ sw;
        aH[ks][0] = *(const uint32_t*)(smem + SM_ZH + rowlo * 128 + oLo);
        aH[ks][1] = *(const uint32_t*)(smem + SM_ZH + rowhi * 128 + oLo);
        aH[ks][2] = *(const uint32_t*)(smem + SM_ZH + rowlo * 128 + oHi);
        aH[ks][3] = *(const uint32_t*)(smem + SM_ZH + rowhi * 128 + oHi);
    }

    const int node0 = nodeBase + rowlo;
    const int node1 = nodeBase + rowhi;
    const float* sB1 = (const float*)(smem + SM_B1);

    #pragma unroll
    for (int pass = 0; pass < 2; pass++) {
        float acc[16][4];
        #pragma unroll
        for (int nt = 0; nt < 16; nt++)
            #pragma unroll
            for (int q = 0; q < 4; q++) acc[nt][q] = 0.f;

        #pragma unroll
        for (int ks = 0; ks < 4; ks++) {
            int k0  = ks * 32 + 4 * cc;
            int oLo = k0 ^ sw, oHi = (k0 + 16) ^ sw;
            #pragma unroll
            for (int nt = 0; nt < 16; nt++) {
                int n = (pass * 16 + nt) * 8 + gr;
                const char* bH = smem + SM_WH + n * 128;
                uint32_t h0 = *(const uint32_t*)(bH + oLo);
                uint32_t h1 = *(const uint32_t*)(bH + oHi);
                mma16816(acc[nt], aH[ks], h0, h1);
            }
        }

        #pragma unroll
        for (int nt = 0; nt < 16; nt++) {
            int ntg = pass * 16 + nt;
            int col = ntg * 8 + 2 * cc;
            float add0 = 0.f, add1 = 0.f;
            __half* dstT;
            int c2;
            if (ntg < 16) { add0 = sB1[col]; add1 = sB1[col + 1]; dstT = g_Ah; c2 = col; }
            else          { dstT = g_Bh; c2 = col - 128; }
            __half2 d0 = __floats2half2_rn(acc[nt][0] + add0, acc[nt][1] + add1);
            __half2 d1 = __floats2half2_rn(acc[nt][2] + add0, acc[nt][3] + add1);
            if (node0 < N_NODES)
                *(uint32_t*)(dstT + (size_t)node0 * NH + c2) = *(const uint32_t*)&d0;
            if (node1 < N_NODES)
                *(uint32_t*)(dstT + (size_t)node1 * NH + c2) = *(const uint32_t*)&d1;
        }
    }
}

// ---------------------------------------------------------------------------
// Kernel 2: edge pass (R10 proven shape). out[e] = W2.relu(A[r]+B[c])+b2
// 8 lanes/edge, 4 edge-slots/warp, unroll-by-2 (8 edges/warp-iter).
// W2 hoisted in 16 regs; add+relu in half2; dot in fp32.
// 128-thread blocks, grid = 148 SM x 10 CTAs = ONE exact persistent wave:
// all 1480 CTAs resident for the whole kernel -> 40 steady warps/SM.
// ---------------------------------------------------------------------------
#define EDGE_BLOCKS 1480

__global__ void __launch_bounds__(128)
edge_kernel(const int* __restrict__ row, const int* __restrict__ col,
            const float* __restrict__ W2, const float* __restrict__ b2,
            float* __restrict__ out) {
    const int lane = threadIdx.x & 31;
    const int warp = threadIdx.x >> 5;
    const int g    = lane >> 3;   // edge slot within warp (0..3)
    const int i    = lane & 7;    // lane within edge (0..7)

    const float4* W24 = (const float4*)W2;
    float4 w4[4];
    #pragma unroll
    for (int q = 0; q < 2; q++)
        #pragma unroll
        for (int h = 0; h < 2; h++)
            w4[q * 2 + h] = W24[(q * 8 + i) * 2 + h];
    const float bias = b2[0];
    const __half2 zero2 = __float2half2_rn(0.f);

    const int warpGlobal = blockIdx.x * 4 + warp;
    const int nWarps     = EDGE_BLOCKS * 4;        // 5920

    // N_EDGES divisible by 8: both sub-iterations always valid
    for (int e0 = warpGlobal * 8; e0 < N_EDGES; e0 += nWarps * 8) {
        const int eA = e0 + g;
        const int eB = e0 + 4 + g;

        const int rA = row[eA], cA = col[eA];
        const int rB = row[eB], cB = col[eB];

        const uint4* __restrict__ ArA = (const uint4*)(g_Ah + (size_t)rA * NH);
        const uint4* __restrict__ BcA = (const uint4*)(g_Bh + (size_t)cA * NH);
        const uint4* __restrict__ ArB = (const uint4*)(g_Ah + (size_t)rB * NH);
        const uint4* __restrict__ BcB = (const uint4*)(g_Bh + (size_t)cB * NH);

        uint4 avA[2], bvA[2], avB[2], bvB[2];
        #pragma unroll
        for (int q = 0; q < 2; q++) {
            avA[q] = ArA[q * 8 + i];  bvA[q] = BcA[q * 8 + i];
            avB[q] = ArB[q * 8 + i];  bvB[q] = BcB[q * 8 + i];
        }

        float sA = 0.f, sB = 0.f;
        #pragma unroll
        for (int q = 0; q < 2; q++) {
            const __half2* ahA = (const __half2*)&avA[q];
            const __half2* bhA = (const __half2*)&bvA[q];
            const __half2* ahB = (const __half2*)&avB[q];
            const __half2* bhB = (const __half2*)&bvB[q];
            const float* wq = (const float*)&w4[q * 2];
            #pragma unroll
            for (int t = 0; t < 4; t++) {
                __half2 hA = __hmax2(__hadd2(ahA[t], bhA[t]), zero2);
                __half2 hB = __hmax2(__hadd2(ahB[t], bhB[t]), zero2);
                float2 fA = __half22float2(hA);
                float2 fB = __half22float2(hB);
                sA += wq[2 * t]     * fA.x;
                sA += wq[2 * t + 1] * fA.y;
                sB += wq[2 * t]     * fB.x;
                sB += wq[2 * t + 1] * fB.y;
            }
        }

        sA += __shfl_xor_sync(0xffffffffu, sA, 1);
        sA += __shfl_xor_sync(0xffffffffu, sA, 2);
        sA += __shfl_xor_sync(0xffffffffu, sA, 4);
        sB += __shfl_xor_sync(0xffffffffu, sB, 1);
        sB += __shfl_xor_sync(0xffffffffu, sB, 2);
        sB += __shfl_xor_sync(0xffffffffu, sB, 4);

        if (i == 0) {
            out[eA] = sA + bias;
            out[eB] = sB + bias;
        }
    }
}

// ---------------------------------------------------------------------------
extern "C" void kernel_launch(void* const* d_in, const int* in_sizes, int n_in,
                              void* d_out, int out_size) {
    const float* z   = (const float*)d_in[0];
    const int*   row = (const int*)  d_in[1];
    const int*   col = (const int*)  d_in[2];
    const float* W1  = (const float*)d_in[3];
    const float* b1  = (const float*)d_in[4];
    const float* W2  = (const float*)d_in[5];
    const float* b2  = (const float*)d_in[6];
    float* out = (float*)d_out;

    cudaFuncSetAttribute(node_mma, cudaFuncAttributeMaxDynamicSharedMemorySize, SM_TOT);

    node_mma<<<(N_NODES + 127) / 128, 256, SM_TOT>>>(z, W1, b1);  // 782 blocks
    edge_kernel<<<EDGE_BLOCKS, 128>>>(row, col, W2, b2, out);     // 1 wave, persistent
}

// round 15
// speedup vs baseline: 1.3285x; 1.3285x over previous
#include <cuda_runtime.h>
#include <cuda_fp16.h>
#include <cstdint>

#define N_NODES 100000
#define N_EDGES 3200000
#define D       64
#define NH      128

// ---------------------------------------------------------------------------
// Scratch (allocation-free rule: __device__ globals)
// ---------------------------------------------------------------------------
__device__ __half g_Ah[(size_t)N_NODES * NH];   // 25.6 MB: W1[:, :64] @ z + b1  (fp16)
__device__ __half g_Bh[(size_t)N_NODES * NH];   // 25.6 MB: W1[:, 64:] @ z       (fp16)

// ---------------------------------------------------------------------------
// smem layout for node_mma (bytes)
// ---------------------------------------------------------------------------
#define SM_B1   0            // 512 B
#define SM_ZH   512          // 16 KB  zh [128 rows][128 B]
#define SM_WH   16896        // 32 KB  Wh [256 rows][128 B]  (fused, swizzled)
#define SM_TOT  49664

// ---------------------------------------------------------------------------
// m16n8k16 fp16 MMA, fp32 accumulators (sm_80+ PTX, portable to compute_103)
// ---------------------------------------------------------------------------
__device__ __forceinline__ void mma16816(float* c, const uint32_t* a,
                                         uint32_t b0, uint32_t b1) {
    asm volatile(
        "mma.sync.aligned.m16n8k16.row.col.f32.f16.f16.f32 "
        "{%0,%1,%2,%3}, {%4,%5,%6,%7}, {%8,%9}, {%0,%1,%2,%3};"
        : "+f"(c[0]), "+f"(c[1]), "+f"(c[2]), "+f"(c[3])
        : "r"(a[0]), "r"(a[1]), "r"(a[2]), "r"(a[3]), "r"(b0), "r"(b1));
}

// ---------------------------------------------------------------------------
// Kernel 1: node GEMM on tensor cores (fused W conversion, single fp16 MMA).
// 256 nodes per CTA in two 128-node halves; W converted ONCE per CTA
// (halves aggregate W1 re-read traffic vs 128-node CTAs).
// Per half: D[128 x 256] = zh[128x64] @ Wh[64x256]  (fp32 accum)
// ---------------------------------------------------------------------------
__global__ void __launch_bounds__(256) node_mma(const float* __restrict__ z,
                                                const float* __restrict__ W1,
                                                const float* __restrict__ b1) {
    extern __shared__ char smem[];
    const int tid  = threadIdx.x;
    const int wid  = tid >> 5;
    const int lane = tid & 31;
    const int gr   = lane >> 2;   // group row 0..7
    const int cc   = lane & 3;    // thread-in-group 0..3

    if (tid < 128) ((float*)(smem + SM_B1))[tid] = b1[tid];

    // Fused W conversion: W1 fp32 -> swizzled fp16 smem (once per CTA)
    #pragma unroll
    for (int it = 0; it < 64; it++) {
        int idx = tid + it * 256;       // 0..16383
        int n = idx >> 6;
        int k = idx & 63;
        float w = (n < 128) ? W1[n * NH + k] : W1[(n - 128) * NH + 64 + k];
        uint32_t off = (uint32_t)(n * 128 + ((k * 2) ^ ((n & 7) << 4)));
        *(__half*)(smem + SM_WH + off) = __float2half_rn(w);
    }

    const float* sB1 = (const float*)(smem + SM_B1);

    for (int half = 0; half < 2; half++) {
        const int nodeBase = blockIdx.x * 256 + half * 128;

        if (half) __syncthreads();   // all zh reads of previous half complete

        // z tile: 128 rows x 64 cols fp32 -> zh fp16, swizzled
        #pragma unroll
        for (int i = 0; i < 16; i++) {
            int p    = tid + i * 256;
            int r    = p >> 5;
            int kp   = p & 31;
            int node = nodeBase + r;
            float2 zv = (node < N_NODES)
                      ? ((const float2*)z)[(size_t)node * 32 + kp]
                      : make_float2(0.f, 0.f);
            __half2 h = __floats2half2_rn(zv.x, zv.y);
            uint32_t off = (uint32_t)(r * 128 + ((4 * kp) ^ ((r & 7) << 4)));
            *(uint32_t*)(smem + SM_ZH + off) = *(const uint32_t*)&h;
        }
        __syncthreads();

        const int rowlo = wid * 16 + gr;
        const int rowhi = rowlo + 8;
        const int sw    = gr << 4;
        uint32_t aH[4][4];
        #pragma unroll
        for (int ks = 0; ks < 4; ks++) {
            int k0 = ks * 32 + 4 * cc;
            int oLo = k0 ^ sw, oHi = (k0 + 16) ^ sw;
            aH[ks][0] = *(const uint32_t*)(smem + SM_ZH + rowlo * 128 + oLo);
            aH[ks][1] = *(const uint32_t*)(smem + SM_ZH + rowhi * 128 + oLo);
            aH[ks][2] = *(const uint32_t*)(smem + SM_ZH + rowlo * 128 + oHi);
            aH[ks][3] = *(const uint32_t*)(smem + SM_ZH + rowhi * 128 + oHi);
        }

        const int node0 = nodeBase + rowlo;
        const int node1 = nodeBase + rowhi;

        #pragma unroll
        for (int pass = 0; pass < 2; pass++) {
            float acc[16][4];
            #pragma unroll
            for (int nt = 0; nt < 16; nt++)
                #pragma unroll
                for (int q = 0; q < 4; q++) acc[nt][q] = 0.f;

            #pragma unroll
            for (int ks = 0; ks < 4; ks++) {
                int k0  = ks * 32 + 4 * cc;
                int oLo = k0 ^ sw, oHi = (k0 + 16) ^ sw;
                #pragma unroll
                for (int nt = 0; nt < 16; nt++) {
                    int n = (pass * 16 + nt) * 8 + gr;
                    const char* bH = smem + SM_WH + n * 128;
                    uint32_t h0 = *(const uint32_t*)(bH + oLo);
                    uint32_t h1 = *(const uint32_t*)(bH + oHi);
                    mma16816(acc[nt], aH[ks], h0, h1);
                }
            }

            #pragma unroll
            for (int nt = 0; nt < 16; nt++) {
                int ntg = pass * 16 + nt;
                int col = ntg * 8 + 2 * cc;
                float add0 = 0.f, add1 = 0.f;
                __half* dstT;
                int c2;
                if (ntg < 16) { add0 = sB1[col]; add1 = sB1[col + 1]; dstT = g_Ah; c2 = col; }
                else          { dstT = g_Bh; c2 = col - 128; }
                __half2 d0 = __floats2half2_rn(acc[nt][0] + add0, acc[nt][1] + add1);
                __half2 d1 = __floats2half2_rn(acc[nt][2] + add0, acc[nt][3] + add1);
                if (node0 < N_NODES)
                    *(uint32_t*)(dstT + (size_t)node0 * NH + c2) = *(const uint32_t*)&d0;
                if (node1 < N_NODES)
                    *(uint32_t*)(dstT + (size_t)node1 * NH + c2) = *(const uint32_t*)&d1;
            }
        }
    }
}

// ---------------------------------------------------------------------------
// Kernel 2: edge pass (R10/R13 proven shape). out[e] = W2.relu(A[r]+B[c])+b2
// 8 lanes/edge, 4 edge-slots/warp, unroll-by-2 (8 edges/warp-iter).
// W2 hoisted in 16 regs; add+relu in half2; dot in fp32; int indices.
// 128-thread blocks, grid 4736 (~3.2 waves of 10 CTA/SM): fine-grained CTA
// refill minimizes the drain tail (R14 showed 1 exact wave is worst-case).
// ---------------------------------------------------------------------------
#define EDGE_BLOCKS 4736

__global__ void __launch_bounds__(128)
edge_kernel(const int* __restrict__ row, const int* __restrict__ col,
            const float* __restrict__ W2, const float* __restrict__ b2,
            float* __restrict__ out) {
    const int lane = threadIdx.x & 31;
    const int warp = threadIdx.x >> 5;
    const int g    = lane >> 3;   // edge slot within warp (0..3)
    const int i    = lane & 7;    // lane within edge (0..7)

    const float4* W24 = (const float4*)W2;
    float4 w4[4];
    #pragma unroll
    for (int q = 0; q < 2; q++)
        #pragma unroll
        for (int h = 0; h < 2; h++)
            w4[q * 2 + h] = W24[(q * 8 + i) * 2 + h];
    const float bias = b2[0];
    const __half2 zero2 = __float2half2_rn(0.f);

    const int warpGlobal = blockIdx.x * 4 + warp;
    const int nWarps     = EDGE_BLOCKS * 4;        // 18944

    // N_EDGES divisible by 8: both sub-iterations always valid
    for (int e0 = warpGlobal * 8; e0 < N_EDGES; e0 += nWarps * 8) {
        const int eA = e0 + g;
        const int eB = e0 + 4 + g;

        const int rA = row[eA], cA = col[eA];
        const int rB = row[eB], cB = col[eB];

        const uint4* __restrict__ ArA = (const uint4*)(g_Ah + (size_t)rA * NH);
        const uint4* __restrict__ BcA = (const uint4*)(g_Bh + (size_t)cA * NH);
        const uint4* __restrict__ ArB = (const uint4*)(g_Ah + (size_t)rB * NH);
        const uint4* __restrict__ BcB = (const uint4*)(g_Bh + (size_t)cB * NH);

        uint4 avA[2], bvA[2], avB[2], bvB[2];
        #pragma unroll
        for (int q = 0; q < 2; q++) {
            avA[q] = ArA[q * 8 + i];  bvA[q] = BcA[q * 8 + i];
            avB[q] = ArB[q * 8 + i];  bvB[q] = BcB[q * 8 + i];
        }

        float sA = 0.f, sB = 0.f;
        #pragma unroll
        for (int q = 0; q < 2; q++) {
            const __half2* ahA = (const __half2*)&avA[q];
            const __half2* bhA = (const __half2*)&bvA[q];
            const __half2* ahB = (const __half2*)&avB[q];
            const __half2* bhB = (const __half2*)&bvB[q];
            const float* wq = (const float*)&w4[q * 2];
            #pragma unroll
            for (int t = 0; t < 4; t++) {
                __half2 hA = __hmax2(__hadd2(ahA[t], bhA[t]), zero2);
                __half2 hB = __hmax2(__hadd2(ahB[t], bhB[t]), zero2);
                float2 fA = __half22float2(hA);
                float2 fB = __half22float2(hB);
                sA += wq[2 * t]     * fA.x;
                sA += wq[2 * t + 1] * fA.y;
                sB += wq[2 * t]     * fB.x;
                sB += wq[2 * t + 1] * fB.y;
            }
        }

        sA += __shfl_xor_sync(0xffffffffu, sA, 1);
        sA += __shfl_xor_sync(0xffffffffu, sA, 2);
        sA += __shfl_xor_sync(0xffffffffu, sA, 4);
        sB += __shfl_xor_sync(0xffffffffu, sB, 1);
        sB += __shfl_xor_sync(0xffffffffu, sB, 2);
        sB += __shfl_xor_sync(0xffffffffu, sB, 4);

        if (i == 0) {
            out[eA] = sA + bias;
            out[eB] = sB + bias;
        }
    }
}

// ---------------------------------------------------------------------------
extern "C" void kernel_launch(void* const* d_in, const int* in_sizes, int n_in,
                              void* d_out, int out_size) {
    const float* z   = (const float*)d_in[0];
    const int*   row = (const int*)  d_in[1];
    const int*   col = (const int*)  d_in[2];
    const float* W1  = (const float*)d_in[3];
    const float* b1  = (const float*)d_in[4];
    const float* W2  = (const float*)d_in[5];
    const float* b2  = (const float*)d_in[6];
    float* out = (float*)d_out;

    cudaFuncSetAttribute(node_mma, cudaFuncAttributeMaxDynamicSharedMemorySize, SM_TOT);

    node_mma<<<(N_NODES + 255) / 256, 256, SM_TOT>>>(z, W1, b1);  // 391 blocks
    edge_kernel<<<EDGE_BLOCKS, 128>>>(row, col, W2, b2, out);     // fine-grained persistent
}

// round 16
// speedup vs baseline: 1.3860x; 1.0433x over previous
#include <cuda_runtime.h>
#include <cuda_fp16.h>
#include <cstdint>

#define N_NODES 100000
#define N_EDGES 3200000
#define D       64
#define NH      128

// ---------------------------------------------------------------------------
// Scratch (allocation-free rule: __device__ globals)
// ---------------------------------------------------------------------------
__device__ __half g_Ah[(size_t)N_NODES * NH];   // 25.6 MB: W1[:, :64] @ z + b1  (fp16)
__device__ __half g_Bh[(size_t)N_NODES * NH];   // 25.6 MB: W1[:, 64:] @ z       (fp16)

// ---------------------------------------------------------------------------
// smem layout for node_mma (bytes)
// ---------------------------------------------------------------------------
#define SM_B1   0            // 512 B
#define SM_ZH   512          // 16 KB  zh [128 rows][128 B]
#define SM_WH   16896        // 32 KB  Wh [256 rows][128 B]  (fused, swizzled)
#define SM_TOT  49664

// ---------------------------------------------------------------------------
// m16n8k16 fp16 MMA, fp32 accumulators (sm_80+ PTX, portable to compute_103)
// ---------------------------------------------------------------------------
__device__ __forceinline__ void mma16816(float* c, const uint32_t* a,
                                         uint32_t b0, uint32_t b1) {
    asm volatile(
        "mma.sync.aligned.m16n8k16.row.col.f32.f16.f16.f32 "
        "{%0,%1,%2,%3}, {%4,%5,%6,%7}, {%8,%9}, {%0,%1,%2,%3};"
        : "+f"(c[0]), "+f"(c[1]), "+f"(c[2]), "+f"(c[3])
        : "r"(a[0]), "r"(a[1]), "r"(a[2]), "r"(a[3]), "r"(b0), "r"(b1));
}

// ---------------------------------------------------------------------------
// Kernel 1: node GEMM on tensor cores (R15 proven form).
// 256 nodes per CTA in two 128-node halves; W converted ONCE per CTA.
// Per half: D[128 x 256] = zh[128x64] @ Wh[64x256]  (fp32 accum)
// ---------------------------------------------------------------------------
__global__ void __launch_bounds__(256) node_mma(const float* __restrict__ z,
                                                const float* __restrict__ W1,
                                                const float* __restrict__ b1) {
    extern __shared__ char smem[];
    const int tid  = threadIdx.x;
    const int wid  = tid >> 5;
    const int lane = tid & 31;
    const int gr   = lane >> 2;   // group row 0..7
    const int cc   = lane & 3;    // thread-in-group 0..3

    if (tid < 128) ((float*)(smem + SM_B1))[tid] = b1[tid];

    // Fused W conversion: W1 fp32 -> swizzled fp16 smem (once per CTA)
    #pragma unroll
    for (int it = 0; it < 64; it++) {
        int idx = tid + it * 256;       // 0..16383
        int n = idx >> 6;
        int k = idx & 63;
        float w = (n < 128) ? W1[n * NH + k] : W1[(n - 128) * NH + 64 + k];
        uint32_t off = (uint32_t)(n * 128 + ((k * 2) ^ ((n & 7) << 4)));
        *(__half*)(smem + SM_WH + off) = __float2half_rn(w);
    }

    const float* sB1 = (const float*)(smem + SM_B1);

    for (int half = 0; half < 2; half++) {
        const int nodeBase = blockIdx.x * 256 + half * 128;

        if (half) __syncthreads();   // all zh reads of previous half complete

        // z tile: 128 rows x 64 cols fp32 -> zh fp16, swizzled
        #pragma unroll
        for (int i = 0; i < 16; i++) {
            int p    = tid + i * 256;
            int r    = p >> 5;
            int kp   = p & 31;
            int node = nodeBase + r;
            float2 zv = (node < N_NODES)
                      ? ((const float2*)z)[(size_t)node * 32 + kp]
                      : make_float2(0.f, 0.f);
            __half2 h = __floats2half2_rn(zv.x, zv.y);
            uint32_t off = (uint32_t)(r * 128 + ((4 * kp) ^ ((r & 7) << 4)));
            *(uint32_t*)(smem + SM_ZH + off) = *(const uint32_t*)&h;
        }
        __syncthreads();

        const int rowlo = wid * 16 + gr;
        const int rowhi = rowlo + 8;
        const int sw    = gr << 4;
        uint32_t aH[4][4];
        #pragma unroll
        for (int ks = 0; ks < 4; ks++) {
            int k0 = ks * 32 + 4 * cc;
            int oLo = k0 ^ sw, oHi = (k0 + 16) ^ sw;
            aH[ks][0] = *(const uint32_t*)(smem + SM_ZH + rowlo * 128 + oLo);
            aH[ks][1] = *(const uint32_t*)(smem + SM_ZH + rowhi * 128 + oLo);
            aH[ks][2] = *(const uint32_t*)(smem + SM_ZH + rowlo * 128 + oHi);
            aH[ks][3] = *(const uint32_t*)(smem + SM_ZH + rowhi * 128 + oHi);
        }

        const int node0 = nodeBase + rowlo;
        const int node1 = nodeBase + rowhi;

        #pragma unroll
        for (int pass = 0; pass < 2; pass++) {
            float acc[16][4];
            #pragma unroll
            for (int nt = 0; nt < 16; nt++)
                #pragma unroll
                for (int q = 0; q < 4; q++) acc[nt][q] = 0.f;

            #pragma unroll
            for (int ks = 0; ks < 4; ks++) {
                int k0  = ks * 32 + 4 * cc;
                int oLo = k0 ^ sw, oHi = (k0 + 16) ^ sw;
                #pragma unroll
                for (int nt = 0; nt < 16; nt++) {
                    int n = (pass * 16 + nt) * 8 + gr;
                    const char* bH = smem + SM_WH + n * 128;
                    uint32_t h0 = *(const uint32_t*)(bH + oLo);
                    uint32_t h1 = *(const uint32_t*)(bH + oHi);
                    mma16816(acc[nt], aH[ks], h0, h1);
                }
            }

            #pragma unroll
            for (int nt = 0; nt < 16; nt++) {
                int ntg = pass * 16 + nt;
                int col = ntg * 8 + 2 * cc;
                float add0 = 0.f, add1 = 0.f;
                __half* dstT;
                int c2;
                if (ntg < 16) { add0 = sB1[col]; add1 = sB1[col + 1]; dstT = g_Ah; c2 = col; }
                else          { dstT = g_Bh; c2 = col - 128; }
                __half2 d0 = __floats2half2_rn(acc[nt][0] + add0, acc[nt][1] + add1);
                __half2 d1 = __floats2half2_rn(acc[nt][2] + add0, acc[nt][3] + add1);
                if (node0 < N_NODES)
                    *(uint32_t*)(dstT + (size_t)node0 * NH + c2) = *(const uint32_t*)&d0;
                if (node1 < N_NODES)
                    *(uint32_t*)(dstT + (size_t)node1 * NH + c2) = *(const uint32_t*)&d1;
            }
        }
    }
}

// ---------------------------------------------------------------------------
// Kernel 2: edge pass with SOFTWARE-PIPELINED index loads.
// out[e] = W2 . relu(A[row]+B[col]) + b2
// 8 lanes/edge, 4 edge-slots/warp, unroll-by-2 (8 edges/warp-iter).
// Iteration n issues its 8 table LDG.128s, then immediately prefetches
// iteration n+1's row/col indices (clamped address on last iter, loads
// unconditional) so the idx DRAM latency overlaps table wait + compute.
// ---------------------------------------------------------------------------
#define EDGE_BLOCKS 4736

__global__ void __launch_bounds__(128)
edge_kernel(const int* __restrict__ row, const int* __restrict__ col,
            const float* __restrict__ W2, const float* __restrict__ b2,
            float* __restrict__ out) {
    const int lane = threadIdx.x & 31;
    const int warp = threadIdx.x >> 5;
    const int g    = lane >> 3;   // edge slot within warp (0..3)
    const int i    = lane & 7;    // lane within edge (0..7)

    const float4* W24 = (const float4*)W2;
    float4 w4[4];
    #pragma unroll
    for (int q = 0; q < 2; q++)
        #pragma unroll
        for (int h = 0; h < 2; h++)
            w4[q * 2 + h] = W24[(q * 8 + i) * 2 + h];
    const float bias = b2[0];
    const __half2 zero2 = __float2half2_rn(0.f);

    const int warpGlobal = blockIdx.x * 4 + warp;
    const int nWarps     = EDGE_BLOCKS * 4;          // 18944
    const int STRIDE     = nWarps * 8;               // 151552

    int e0 = warpGlobal * 8;                         // always < N_EDGES
    // preload first iteration's indices
    int rA = row[e0 + g],     cA = col[e0 + g];
    int rB = row[e0 + 4 + g], cB = col[e0 + 4 + g];

    for (; e0 < N_EDGES; ) {
        const int eNext = e0 + STRIDE;
        const int eSafe = (eNext < N_EDGES) ? eNext : 0;   // clamp: loads stay unconditional

        // issue table loads for CURRENT iteration first
        const uint4* __restrict__ ArA = (const uint4*)(g_Ah + (size_t)rA * NH);
        const uint4* __restrict__ BcA = (const uint4*)(g_Bh + (size_t)cA * NH);
        const uint4* __restrict__ ArB = (const uint4*)(g_Ah + (size_t)rB * NH);
        const uint4* __restrict__ BcB = (const uint4*)(g_Bh + (size_t)cB * NH);

        uint4 avA[2], bvA[2], avB[2], bvB[2];
        #pragma unroll
        for (int q = 0; q < 2; q++) {
            avA[q] = ArA[q * 8 + i];  bvA[q] = BcA[q * 8 + i];
            avB[q] = ArB[q * 8 + i];  bvB[q] = BcB[q * 8 + i];
        }

        // prefetch NEXT iteration's indices (overlaps with table-load latency)
        const int nrA = row[eSafe + g],     ncA = col[eSafe + g];
        const int nrB = row[eSafe + 4 + g], ncB = col[eSafe + 4 + g];

        float sA = 0.f, sB = 0.f;
        #pragma unroll
        for (int q = 0; q < 2; q++) {
            const __half2* ahA = (const __half2*)&avA[q];
            const __half2* bhA = (const __half2*)&bvA[q];
            const __half2* ahB = (const __half2*)&avB[q];
            const __half2* bhB = (const __half2*)&bvB[q];
            const float* wq = (const float*)&w4[q * 2];
            #pragma unroll
            for (int t = 0; t < 4; t++) {
                __half2 hA = __hmax2(__hadd2(ahA[t], bhA[t]), zero2);
                __half2 hB = __hmax2(__hadd2(ahB[t], bhB[t]), zero2);
                float2 fA = __half22float2(hA);
                float2 fB = __half22float2(hB);
                sA += wq[2 * t]     * fA.x;
                sA += wq[2 * t + 1] * fA.y;
                sB += wq[2 * t]     * fB.x;
                sB += wq[2 * t + 1] * fB.y;
            }
        }

        sA += __shfl_xor_sync(0xffffffffu, sA, 1);
        sA += __shfl_xor_sync(0xffffffffu, sA, 2);
        sA += __shfl_xor_sync(0xffffffffu, sA, 4);
        sB += __shfl_xor_sync(0xffffffffu, sB, 1);
        sB += __shfl_xor_sync(0xffffffffu, sB, 2);
        sB += __shfl_xor_sync(0xffffffffu, sB, 4);

        if (i == 0) {
            out[e0 + g]     = sA + bias;
            out[e0 + 4 + g] = sB + bias;
        }

        rA = nrA; cA = ncA; rB = nrB; cB = ncB;
        e0 = eNext;
    }
}

// ---------------------------------------------------------------------------
extern "C" void kernel_launch(void* const* d_in, const int* in_sizes, int n_in,
                              void* d_out, int out_size) {
    const float* z   = (const float*)d_in[0];
    const int*   row = (const int*)  d_in[1];
    const int*   col = (const int*)  d_in[2];
    const float* W1  = (const float*)d_in[3];
    const float* b1  = (const float*)d_in[4];
    const float* W2  = (const float*)d_in[5];
    const float* b2  = (const float*)d_in[6];
    float* out = (float*)d_out;

    cudaFuncSetAttribute(node_mma, cudaFuncAttributeMaxDynamicSharedMemorySize, SM_TOT);

    node_mma<<<(N_NODES + 255) / 256, 256, SM_TOT>>>(z, W1, b1);  // 391 blocks
    edge_kernel<<<EDGE_BLOCKS, 128>>>(row, col, W2, b2, out);     // pipelined persistent
}